// round 7
// baseline (speedup 1.0000x reference)
#include <cuda_runtime.h>
#include <cuda_bf16.h>

#define B_ 4
#define H_ 224
#define W_ 224
#define C_ 64
#define K_ 8
#define EPS_ 1e-6f

#define H2_W 226            // H2 idx s: window cols [s-1, s] clipped, s in [0,226)
#define H8_W 232            // H8 idx u: window cols [u-7, u] clipped, u in [0,232)
#define ST2 (H2_W * C_)
#define ST8 (H8_W * C_)
#define STX (W_ * C_)
#define CH_ 56              // rows per kB chunk (4 chunks)

__device__ float g_H2[(size_t)B_ * H_ * H2_W * C_];
__device__ float g_H8[(size_t)B_ * H_ * H8_W * C_];
__device__ float g_mn[B_], g_mx[B_];

static __device__ __forceinline__ void atomicMinF(float* a, float v) {
    if (v >= 0.f) atomicMin((int*)a, __float_as_int(v));
    else          atomicMax((unsigned int*)a, __float_as_uint(v));
}
static __device__ __forceinline__ void atomicMaxF(float* a, float v) {
    if (v >= 0.f) atomicMax((int*)a, __float_as_int(v));
    else          atomicMin((unsigned int*)a, __float_as_uint(v));
}

__global__ void k_init() {
    if (threadIdx.x < B_) {
        g_mn[threadIdx.x] = __int_as_float(0x7f800000);   // +inf
        g_mx[threadIdx.x] = __int_as_float(0xff800000);   // -inf
    }
}

// Fused: min/max + horizontal 2-sum + horizontal 8-sum (RAW x sums, no scaling)
__global__ void __launch_bounds__(256) kA(const float* __restrict__ x) {
    extern __shared__ float sx[];                  // 224*64 floats = 57344 B
    const int t = blockIdx.x, b = blockIdx.y;
    const int c = threadIdx.x;                     // 0..63
    const int tid = threadIdx.y * 64 + threadIdx.x;

    const float4* xr4 = (const float4*)(x + ((size_t)b * H_ + t) * W_ * C_);
    float4* sx4 = (float4*)sx;
    float mn = 3.402823466e38f, mx = -3.402823466e38f;
    #pragma unroll 4
    for (int i = tid; i < (W_ * C_ / 4); i += 256) {
        float4 v = xr4[i];
        sx4[i] = v;
        mn = fminf(mn, fminf(fminf(v.x, v.y), fminf(v.z, v.w)));
        mx = fmaxf(mx, fmaxf(fmaxf(v.x, v.y), fmaxf(v.z, v.w)));
    }
    #pragma unroll
    for (int o = 16; o; o >>= 1) {
        mn = fminf(mn, __shfl_xor_sync(0xffffffffu, mn, o));
        mx = fmaxf(mx, __shfl_xor_sync(0xffffffffu, mx, o));
    }
    __shared__ float smn[8], smx[8];
    if ((tid & 31) == 0) { smn[tid >> 5] = mn; smx[tid >> 5] = mx; }
    __syncthreads();                               // also publishes sx
    if (tid == 0) {
        #pragma unroll
        for (int i = 1; i < 8; i++) { mn = fminf(mn, smn[i]); mx = fmaxf(mx, smx[i]); }
        atomicMinF(&g_mn[b], mn);
        atomicMaxF(&g_mx[b], mx);
    }

    // H2: cols [s-1, s] clipped to [0, 223]
    float* h2g = g_H2 + (((size_t)b * H_ + t) * H2_W) * C_ + c;
    for (int s = threadIdx.y; s < H2_W; s += 4) {
        float sum;
        if (s >= 1 && s <= 223)  sum = sx[(s - 1) * C_ + c] + sx[s * C_ + c];
        else if (s == 0)         sum = sx[c];
        else if (s == 224)       sum = sx[223 * C_ + c];
        else                     sum = 0.f;        // s == 225
        h2g[s * C_] = sum;
    }

    // H8: cols [u-7, u] clipped to [0, 223]
    float* h8g = g_H8 + (((size_t)b * H_ + t) * H8_W) * C_ + c;
    for (int u = threadIdx.y; u < H8_W; u += 4) {
        float sum = 0.f;
        if (u >= 7 && u <= 223) {
            const float* p = sx + (u - 7) * C_ + c;
            sum = ((p[0] + p[64]) + (p[128] + p[192]))
                + ((p[256] + p[320]) + (p[384] + p[448]));
        } else {
            int lo = max(u - 7, 0), hi = min(u, 223);
            for (int q = lo; q <= hi; q++) sum += sx[q * C_ + c];
        }
        h8g[u * C_] = sum;
    }
}

__global__ void __launch_bounds__(64) kB(
    const float* __restrict__ x,    const float* __restrict__ olsw,
    const float* __restrict__ anch, const float* __restrict__ wdth,
    const float* __restrict__ gmm,  const float* __restrict__ bta,
    const float* __restrict__ mea,  const float* __restrict__ vrr,
    float* __restrict__ out)
{
    const int c = threadIdx.x;
    const int j = blockIdx.x;
    const int i0 = blockIdx.y * CH_;
    const int b = blockIdx.z;

    // OLS slope coefficients
    const float w0 = olsw[0], w1 = olsw[1], w2 = olsw[2], w3 = olsw[3];
    const float L1 = 0.69314718f, L2 = 1.38629436f, L3 = 2.07944154f, L4 = 2.77258872f;
    const float wsum = w0 + w1 + w2 + w3;
    const float lrb = (w0 * L1 + w1 * L2 + w2 * L3 + w3 * L4) / wsum;
    const float d0 = L1 - lrb, d1 = L2 - lrb, d2 = L3 - lrb, d3 = L4 - lrb;
    const float den = w0 * d0 * d0 + w1 * d1 * d1 + w2 * d2 * d2 + w3 * d3 * d3;
    const float ivd = 1.f / den;
    const float c0 = w0 * d0 * ivd, c1 = w1 * d1 * ivd, c2 = w2 * d2 * ivd, c3 = w3 * d3 * ivd;

    const float bsc = gmm[c] * rsqrtf(vrr[c] + 1e-3f);
    const float bsh = bta[c] - mea[c] * bsc;

    float an[K_], wd[K_];
    #pragma unroll
    for (int k = 0; k < K_; k++) { an[k] = anch[c * K_ + k]; wd[k] = wdth[c * K_ + k]; }

    // scaling: m + eps = fma(rawsum, inv, eps - n*mn*inv)
    const float mnv = g_mn[b];
    const float inv = 1.f / (g_mx[b] - mnv + EPS_);
    const float mi  = mnv * inv;
    const float nc2  = (float)(min(j + 1, 223) - j + 1);
    const float nc4  = (float)(min(j + 2, 223) - max(j - 1, 0) + 1);
    const float nc8  = (float)(min(j + 4, 223) - max(j - 3, 0) + 1);
    const float nc16 = (float)(min(j + 8, 223) - max(j - 7, 0) + 1);

    __shared__ float4 s_tab[H_];
    for (int i = c; i < H_; i += 64) {
        float nr2  = (float)(min(i + 1, 223) - i + 1);
        float nr4  = (float)(min(i + 2, 223) - max(i - 1, 0) + 1);
        float nr8  = (float)(min(i + 4, 223) - max(i - 3, 0) + 1);
        float nr16 = (float)(min(i + 8, 223) - max(i - 7, 0) + 1);
        s_tab[i] = make_float4(EPS_ - nr2 * nc2 * mi,  EPS_ - nr4 * nc4 * mi,
                               EPS_ - nr8 * nc8 * mi,  EPS_ - nr16 * nc16 * mi);
    }
    __syncthreads();

    const size_t bh2 = (size_t)b * H_ * ST2;
    const size_t bh8 = (size_t)b * H_ * ST8;
    const float* p2   = g_H2 + bh2 + (j + 1) * C_ + c;
    const float* p4a  = g_H2 + bh2 + (j    ) * C_ + c;
    const float* p4b  = g_H2 + bh2 + (j + 2) * C_ + c;
    const float* p8   = g_H8 + bh8 + (j + 4) * C_ + c;
    const float* p16a = g_H8 + bh8 + (j    ) * C_ + c;
    const float* p16b = g_H8 + bh8 + (j + 8) * C_ + c;
    const float* xr   = x   + ((size_t)b * H_ * W_ + j) * C_ + c;
    float*       orr  = out + ((size_t)b * H_ * W_ + j) * C_ + c;

    float r2[2], r4[4], r8[8], r16[16];

    #pragma unroll
    for (int d = -7; d <= 7; d++) {
        const int t = i0 + d;
        const bool v = (t >= 0);
        r16[d + 7] = v ? (p16a[t * ST8] + p16b[t * ST8]) : 0.f;
        if (d >= -3 && d <= 3) r8[d + 3] = v ? p8[t * ST8] : 0.f;
        if (d >= -1 && d <= 1) r4[d + 1] = v ? (p4a[t * ST2] + p4b[t * ST2]) : 0.f;
        if (d == 0)            r2[0]     = v ? p2[t * ST2] : 0.f;
    }

    for (int base = 0; base < CH_; base += 16) {
        #pragma unroll
        for (int u = 0; u < 16; u++) {
            if (base + u >= CH_) break;
            const int i = i0 + base + u;
            const int t16 = i + 8, t8 = i + 4, t4 = i + 2, t2 = i + 1;
            r16[(15 + u) & 15] = (t16 < H_) ? (p16a[t16 * ST8] + p16b[t16 * ST8]) : 0.f;
            r8 [(7 + u) & 7]   = (t8  < H_) ? p8[t8 * ST8] : 0.f;
            r4 [(3 + u) & 3]   = (t4  < H_) ? (p4a[t4 * ST2] + p4b[t4 * ST2]) : 0.f;
            r2 [(1 + u) & 1]   = (t2  < H_) ? p2[t2 * ST2] : 0.f;

            const float m2 = r2[0] + r2[1];
            const float m4 = (r4[0] + r4[1]) + (r4[2] + r4[3]);
            const float m8 = ((r8[0] + r8[1]) + (r8[2] + r8[3]))
                           + ((r8[4] + r8[5]) + (r8[6] + r8[7]));
            const float m16 = (((r16[0] + r16[1]) + (r16[2] + r16[3]))
                            +  ((r16[4] + r16[5]) + (r16[6] + r16[7])))
                            + (((r16[8] + r16[9]) + (r16[10] + r16[11]))
                            +  ((r16[12] + r16[13]) + (r16[14] + r16[15])));

            const float4 tb = s_tab[i];
            const float ly0 = __logf(fmaf(m2,  inv, tb.x));
            const float ly1 = __logf(fmaf(m4,  inv, tb.y));
            const float ly2 = __logf(fmaf(m8,  inv, tb.z));
            const float ly3 = __logf(fmaf(m16, inv, tb.w));
            const float alpha = fmaf(c3, ly3, fmaf(c2, ly2, fmaf(c1, ly1, c0 * ly0)));
            const float a = fmaf(alpha, bsc, bsh);

            float cnt = 0.f;
            #pragma unroll
            for (int k = 0; k < K_; k++) {
                float h = fmaf(-wd[k], fabsf(a - an[k]), 1.f);
                cnt += fmaxf(h, 0.f);
            }
            const float sig = __fdividef(1.f, 1.f + __expf(-cnt));
            orr[i * STX] = xr[i * STX] + sig;
        }
    }
}

extern "C" void kernel_launch(void* const* d_in, const int* in_sizes, int n_in,
                              void* d_out, int out_size) {
    const float* x    = (const float*)d_in[0];
    const float* olsw = (const float*)d_in[1];
    const float* anch = (const float*)d_in[2];
    const float* wdth = (const float*)d_in[3];
    const float* gmm  = (const float*)d_in[4];
    const float* bta  = (const float*)d_in[5];
    const float* mea  = (const float*)d_in[6];
    const float* vrr  = (const float*)d_in[7];
    float* out = (float*)d_out;

    cudaFuncSetAttribute(kA, cudaFuncAttributeMaxDynamicSharedMemorySize, W_ * C_ * 4);

    k_init<<<1, 32>>>();
    kA<<<dim3(H_, B_), dim3(C_, 4), W_ * C_ * 4>>>(x);
    kB<<<dim3(W_, H_ / CH_, B_), C_>>>(x, olsw, anch, wdth, gmm, bta, mea, vrr, out);
}

// round 8
// speedup vs baseline: 1.0671x; 1.0671x over previous
#include <cuda_runtime.h>
#include <cuda_bf16.h>

#define B_ 4
#define H_ 224
#define W_ 224
#define C_ 64
#define K_ 8
#define EPS_ 1e-6f

#define H2_W 226            // H2 idx s: window cols [s-1, s] zero-padded
#define H8_W 232            // H8 idx u: window cols [u-7, u] zero-padded
#define ST2 (H2_W * C_)
#define ST8 (H8_W * C_)
#define STX (W_ * C_)
#define CH_ 56              // rows per kB chunk (4 chunks)

__device__ float g_H2[(size_t)B_ * H_ * H2_W * C_];
__device__ float g_H8[(size_t)B_ * H_ * H8_W * C_];
__device__ float g_mn[B_], g_mx[B_];

static __device__ __forceinline__ void atomicMinF(float* a, float v) {
    if (v >= 0.f) atomicMin((int*)a, __float_as_int(v));
    else          atomicMax((unsigned int*)a, __float_as_uint(v));
}
static __device__ __forceinline__ void atomicMaxF(float* a, float v) {
    if (v >= 0.f) atomicMax((int*)a, __float_as_int(v));
    else          atomicMin((unsigned int*)a, __float_as_uint(v));
}

__global__ void k_init() {
    if (threadIdx.x < B_) {
        g_mn[threadIdx.x] = __int_as_float(0x7f800000);   // +inf
        g_mx[threadIdx.x] = __int_as_float(0xff800000);   // -inf
    }
}

// One-pass streaming front-end: min/max + H2 + H8 (RAW sums; scaling done in kB).
// Thread = one (b, row, channel) lane; register ring over columns.
__global__ void __launch_bounds__(128) kA(const float* __restrict__ x) {
    const int c = threadIdx.x;                       // 0..63
    const int t = blockIdx.x * 2 + threadIdx.y;      // row
    const int b = blockIdx.y;

    const float* xr  = x    + (((size_t)b * H_ + t) * W_  ) * C_ + c;
    float*       h2g = g_H2 + (((size_t)b * H_ + t) * H2_W) * C_ + c;
    float*       h8g = g_H8 + (((size_t)b * H_ + t) * H8_W) * C_ + c;

    float mn = 3.402823466e38f, mx = -3.402823466e38f;
    float xprev = 0.f;
    float ring[8];
    #pragma unroll
    for (int i = 0; i < 8; i++) ring[i] = 0.f;

    for (int base = 0; base < H8_W; base += 8) {     // 232 = 29*8
        #pragma unroll
        for (int uu = 0; uu < 8; uu++) {
            const int u = base + uu;
            float xc = 0.f;
            if (u <= 223) {
                xc = xr[u * C_];
                mn = fminf(mn, xc);
                mx = fmaxf(mx, xc);
            }
            const float h2 = xprev + xc;
            xprev = xc;
            ring[u & 7] = h2;
            const float h8 = (h2 + ring[(u - 2) & 7])
                           + (ring[(u - 4) & 7] + ring[(u - 6) & 7]);
            if (u <= 225) h2g[u * C_] = h2;
            h8g[u * C_] = h8;
        }
    }

    // block reduce min/max -> atomics
    #pragma unroll
    for (int o = 16; o; o >>= 1) {
        mn = fminf(mn, __shfl_xor_sync(0xffffffffu, mn, o));
        mx = fmaxf(mx, __shfl_xor_sync(0xffffffffu, mx, o));
    }
    __shared__ float smn[4], smx[4];
    const int tid = threadIdx.y * 64 + threadIdx.x;
    if ((tid & 31) == 0) { smn[tid >> 5] = mn; smx[tid >> 5] = mx; }
    __syncthreads();
    if (tid == 0) {
        #pragma unroll
        for (int i = 1; i < 4; i++) { mn = fminf(mn, smn[i]); mx = fmaxf(mx, smx[i]); }
        atomicMinF(&g_mn[b], mn);
        atomicMaxF(&g_mx[b], mx);
    }
}

__global__ void __launch_bounds__(64) kB(
    const float* __restrict__ x,    const float* __restrict__ olsw,
    const float* __restrict__ anch, const float* __restrict__ wdth,
    const float* __restrict__ gmm,  const float* __restrict__ bta,
    const float* __restrict__ mea,  const float* __restrict__ vrr,
    float* __restrict__ out)
{
    const int c = threadIdx.x;
    const int j = blockIdx.x;
    const int i0 = blockIdx.y * CH_;
    const int b = blockIdx.z;

    const float w0 = olsw[0], w1 = olsw[1], w2 = olsw[2], w3 = olsw[3];
    const float L1 = 0.69314718f, L2 = 1.38629436f, L3 = 2.07944154f, L4 = 2.77258872f;
    const float wsum = w0 + w1 + w2 + w3;
    const float lrb = (w0 * L1 + w1 * L2 + w2 * L3 + w3 * L4) / wsum;
    const float d0 = L1 - lrb, d1 = L2 - lrb, d2 = L3 - lrb, d3 = L4 - lrb;
    const float den = w0 * d0 * d0 + w1 * d1 * d1 + w2 * d2 * d2 + w3 * d3 * d3;
    const float ivd = 1.f / den;
    const float c0 = w0 * d0 * ivd, c1 = w1 * d1 * ivd, c2 = w2 * d2 * ivd, c3 = w3 * d3 * ivd;

    const float bsc = gmm[c] * rsqrtf(vrr[c] + 1e-3f);
    const float bsh = bta[c] - mea[c] * bsc;

    float an[K_], wd[K_];
    #pragma unroll
    for (int k = 0; k < K_; k++) { an[k] = anch[c * K_ + k]; wd[k] = wdth[c * K_ + k]; }

    // scaling: m + eps = fma(rawsum, inv, eps - n*mn*inv)
    const float mnv = g_mn[b];
    const float inv = 1.f / (g_mx[b] - mnv + EPS_);
    const float mi  = mnv * inv;
    const float nc2  = (float)(min(j + 1, 223) - j + 1);
    const float nc4  = (float)(min(j + 2, 223) - max(j - 1, 0) + 1);
    const float nc8  = (float)(min(j + 4, 223) - max(j - 3, 0) + 1);
    const float nc16 = (float)(min(j + 8, 223) - max(j - 7, 0) + 1);

    __shared__ float4 s_tab[H_];
    for (int i = c; i < H_; i += 64) {
        float nr2  = (float)(min(i + 1, 223) - i + 1);
        float nr4  = (float)(min(i + 2, 223) - max(i - 1, 0) + 1);
        float nr8  = (float)(min(i + 4, 223) - max(i - 3, 0) + 1);
        float nr16 = (float)(min(i + 8, 223) - max(i - 7, 0) + 1);
        s_tab[i] = make_float4(EPS_ - nr2 * nc2 * mi,  EPS_ - nr4 * nc4 * mi,
                               EPS_ - nr8 * nc8 * mi,  EPS_ - nr16 * nc16 * mi);
    }
    __syncthreads();

    const size_t bh2 = (size_t)b * H_ * ST2;
    const size_t bh8 = (size_t)b * H_ * ST8;
    const float* p2   = g_H2 + bh2 + (j + 1) * C_ + c;
    const float* p4a  = g_H2 + bh2 + (j    ) * C_ + c;
    const float* p4b  = g_H2 + bh2 + (j + 2) * C_ + c;
    const float* p8   = g_H8 + bh8 + (j + 4) * C_ + c;
    const float* p16a = g_H8 + bh8 + (j    ) * C_ + c;
    const float* p16b = g_H8 + bh8 + (j + 8) * C_ + c;
    const float* xr   = x   + ((size_t)b * H_ * W_ + j) * C_ + c;
    float*       orr  = out + ((size_t)b * H_ * W_ + j) * C_ + c;

    float r2[2], r4[4], r8[8], r16[16];

    #pragma unroll
    for (int d = -7; d <= 7; d++) {
        const int t = i0 + d;
        const bool v = (t >= 0);
        r16[d + 7] = v ? (p16a[t * ST8] + p16b[t * ST8]) : 0.f;
        if (d >= -3 && d <= 3) r8[d + 3] = v ? p8[t * ST8] : 0.f;
        if (d >= -1 && d <= 1) r4[d + 1] = v ? (p4a[t * ST2] + p4b[t * ST2]) : 0.f;
        if (d == 0)            r2[0]     = v ? p2[t * ST2] : 0.f;
    }

    for (int base = 0; base < CH_; base += 16) {
        #pragma unroll
        for (int u = 0; u < 16; u++) {
            if (base + u >= CH_) break;
            const int i = i0 + base + u;
            const int t16 = i + 8, t8 = i + 4, t4 = i + 2, t2 = i + 1;
            r16[(15 + u) & 15] = (t16 < H_) ? (p16a[t16 * ST8] + p16b[t16 * ST8]) : 0.f;
            r8 [(7 + u) & 7]   = (t8  < H_) ? p8[t8 * ST8] : 0.f;
            r4 [(3 + u) & 3]   = (t4  < H_) ? (p4a[t4 * ST2] + p4b[t4 * ST2]) : 0.f;
            r2 [(1 + u) & 1]   = (t2  < H_) ? p2[t2 * ST2] : 0.f;

            const float m2 = r2[0] + r2[1];
            const float m4 = (r4[0] + r4[1]) + (r4[2] + r4[3]);
            const float m8 = ((r8[0] + r8[1]) + (r8[2] + r8[3]))
                           + ((r8[4] + r8[5]) + (r8[6] + r8[7]));
            const float m16 = (((r16[0] + r16[1]) + (r16[2] + r16[3]))
                            +  ((r16[4] + r16[5]) + (r16[6] + r16[7])))
                            + (((r16[8] + r16[9]) + (r16[10] + r16[11]))
                            +  ((r16[12] + r16[13]) + (r16[14] + r16[15])));

            const float4 tb = s_tab[i];
            const float ly0 = __logf(fmaf(m2,  inv, tb.x));
            const float ly1 = __logf(fmaf(m4,  inv, tb.y));
            const float ly2 = __logf(fmaf(m8,  inv, tb.z));
            const float ly3 = __logf(fmaf(m16, inv, tb.w));
            const float alpha = fmaf(c3, ly3, fmaf(c2, ly2, fmaf(c1, ly1, c0 * ly0)));
            const float a = fmaf(alpha, bsc, bsh);

            float cnt = 0.f;
            #pragma unroll
            for (int k = 0; k < K_; k++) {
                float h = fmaf(-wd[k], fabsf(a - an[k]), 1.f);
                cnt += fmaxf(h, 0.f);
            }
            const float sig = __fdividef(1.f, 1.f + __expf(-cnt));
            orr[i * STX] = xr[i * STX] + sig;
        }
    }
}

extern "C" void kernel_launch(void* const* d_in, const int* in_sizes, int n_in,
                              void* d_out, int out_size) {
    const float* x    = (const float*)d_in[0];
    const float* olsw = (const float*)d_in[1];
    const float* anch = (const float*)d_in[2];
    const float* wdth = (const float*)d_in[3];
    const float* gmm  = (const float*)d_in[4];
    const float* bta  = (const float*)d_in[5];
    const float* mea  = (const float*)d_in[6];
    const float* vrr  = (const float*)d_in[7];
    float* out = (float*)d_out;

    k_init<<<1, 32>>>();
    kA<<<dim3(H_ / 2, B_), dim3(C_, 2)>>>(x);
    kB<<<dim3(W_, H_ / CH_, B_), C_>>>(x, olsw, anch, wdth, gmm, bta, mea, vrr, out);
}

// round 9
// speedup vs baseline: 1.1341x; 1.0629x over previous
#include <cuda_runtime.h>
#include <cuda_bf16.h>

#define B_ 4
#define H_ 224
#define W_ 224
#define C_ 64
#define K_ 8
#define EPS_ 1e-6f

#define H2_W 226            // H2 idx s: window cols [s-1, s] zero-padded
#define H8_W 232            // H8 idx u: window cols [u-7, u] zero-padded
#define ST2 (H2_W * C_)
#define ST8 (H8_W * C_)
#define STX (W_ * C_)
#define CH_ 56              // rows per kB chunk (4 chunks)

__device__ float g_H2[(size_t)B_ * H_ * H2_W * C_];
__device__ float g_H8[(size_t)B_ * H_ * H8_W * C_];
__device__ float g_rmn[B_ * H_], g_rmx[B_ * H_];

// One-pass streaming front-end: per-row min/max + H2 + H8 (RAW sums).
// Block = one (b,row); threadIdx.y = column segment (u0 = seg*64, 8-aligned).
__global__ void __launch_bounds__(256) kA(const float* __restrict__ x) {
    const int c = threadIdx.x;                  // 0..63
    const int seg = threadIdx.y;                // 0..3
    const int t = blockIdx.x;                   // row
    const int b = blockIdx.y;

    const float* xr  = x    + (((size_t)b * H_ + t) * W_  ) * C_ + c;
    float*       h2g = g_H2 + (((size_t)b * H_ + t) * H2_W) * C_ + c;
    float*       h8g = g_H8 + (((size_t)b * H_ + t) * H8_W) * C_ + c;

    const int u0  = seg * 64;
    const int len = (seg == 3) ? (H8_W - 192) : 64;    // 40 : 64

    float mn = 3.402823466e38f, mx = -3.402823466e38f;
    float ring[8];
    #pragma unroll
    for (int i = 0; i < 8; i++) ring[i] = 0.f;

    // warmup: fill ring with h2(u0-7 .. u0-1), set xprev = x[u0-1]
    float xprev;
    {
        int up = u0 - 8;
        float xp = (up >= 0 && up <= 223) ? xr[up * C_] : 0.f;
        #pragma unroll
        for (int d = -7; d <= -1; d++) {
            const int u = u0 + d;
            float xc = (u >= 0 && u <= 223) ? xr[u * C_] : 0.f;
            ring[(d + 8) & 7] = xp + xc;        // (u0+d)&7 == (d+8)&7 (u0 mult of 8)
            xp = xc;
        }
        xprev = xp;
    }

    for (int base = 0; base < len; base += 8) {
        #pragma unroll
        for (int vv = 0; vv < 8; vv++) {
            const int v = base + vv;
            const int u = u0 + v;
            float xc = 0.f;
            if (u <= 223) {
                xc = xr[u * C_];
                mn = fminf(mn, xc);
                mx = fmaxf(mx, xc);
            }
            const float h2 = xprev + xc;
            xprev = xc;
            ring[v & 7] = h2;
            const float h8 = (h2 + ring[(v - 2) & 7])
                           + (ring[(v - 4) & 7] + ring[(v - 6) & 7]);
            if (u <= 225) h2g[u * C_] = h2;
            h8g[u * C_] = h8;
        }
    }

    // block-reduce row min/max (no atomics; block == one row)
    #pragma unroll
    for (int o = 16; o; o >>= 1) {
        mn = fminf(mn, __shfl_xor_sync(0xffffffffu, mn, o));
        mx = fmaxf(mx, __shfl_xor_sync(0xffffffffu, mx, o));
    }
    __shared__ float smn[8], smx[8];
    const int tid = threadIdx.y * 64 + threadIdx.x;
    if ((tid & 31) == 0) { smn[tid >> 5] = mn; smx[tid >> 5] = mx; }
    __syncthreads();
    if (tid == 0) {
        #pragma unroll
        for (int i = 1; i < 8; i++) { mn = fminf(mn, smn[i]); mx = fmaxf(mx, smx[i]); }
        g_rmn[b * H_ + t] = mn;
        g_rmx[b * H_ + t] = mx;
    }
}

__global__ void __launch_bounds__(64) kB(
    const float* __restrict__ x,    const float* __restrict__ olsw,
    const float* __restrict__ anch, const float* __restrict__ wdth,
    const float* __restrict__ gmm,  const float* __restrict__ bta,
    const float* __restrict__ mea,  const float* __restrict__ vrr,
    float* __restrict__ out)
{
    const int c = threadIdx.x;
    const int j = blockIdx.x;
    const int i0 = blockIdx.y * CH_;
    const int b = blockIdx.z;

    // reduce per-row min/max -> sample min/max
    float mn = 3.402823466e38f, mx = -3.402823466e38f;
    for (int i = c; i < H_; i += 64) {
        mn = fminf(mn, g_rmn[b * H_ + i]);
        mx = fmaxf(mx, g_rmx[b * H_ + i]);
    }
    #pragma unroll
    for (int o = 16; o; o >>= 1) {
        mn = fminf(mn, __shfl_xor_sync(0xffffffffu, mn, o));
        mx = fmaxf(mx, __shfl_xor_sync(0xffffffffu, mx, o));
    }
    __shared__ float sred[4];
    if ((c & 31) == 0) { sred[(c >> 5)] = mn; sred[(c >> 5) + 2] = mx; }
    __syncthreads();
    mn = fminf(sred[0], sred[1]);
    mx = fmaxf(sred[2], sred[3]);

    const float w0 = olsw[0], w1 = olsw[1], w2 = olsw[2], w3 = olsw[3];
    const float L1 = 0.69314718f, L2 = 1.38629436f, L3 = 2.07944154f, L4 = 2.77258872f;
    const float wsum = w0 + w1 + w2 + w3;
    const float lrb = (w0 * L1 + w1 * L2 + w2 * L3 + w3 * L4) / wsum;
    const float d0 = L1 - lrb, d1 = L2 - lrb, d2 = L3 - lrb, d3 = L4 - lrb;
    const float den = w0 * d0 * d0 + w1 * d1 * d1 + w2 * d2 * d2 + w3 * d3 * d3;
    const float ivd = 1.f / den;
    const float c0 = w0 * d0 * ivd, c1 = w1 * d1 * ivd, c2 = w2 * d2 * ivd, c3 = w3 * d3 * ivd;

    const float bsc = gmm[c] * rsqrtf(vrr[c] + 1e-3f);
    const float bsh = bta[c] - mea[c] * bsc;

    float an[K_], wd[K_];
    #pragma unroll
    for (int k = 0; k < K_; k++) { an[k] = anch[c * K_ + k]; wd[k] = wdth[c * K_ + k]; }

    // scaling: m + eps = fma(rawsum, inv, eps - n*mn*inv)
    const float inv = 1.f / (mx - mn + EPS_);
    const float mi  = mn * inv;
    const float nc2  = (float)(min(j + 1, 223) - j + 1);
    const float nc4  = (float)(min(j + 2, 223) - max(j - 1, 0) + 1);
    const float nc8  = (float)(min(j + 4, 223) - max(j - 3, 0) + 1);
    const float nc16 = (float)(min(j + 8, 223) - max(j - 7, 0) + 1);

    __shared__ float4 s_tab[H_];
    for (int i = c; i < H_; i += 64) {
        float nr2  = (float)(min(i + 1, 223) - i + 1);
        float nr4  = (float)(min(i + 2, 223) - max(i - 1, 0) + 1);
        float nr8  = (float)(min(i + 4, 223) - max(i - 3, 0) + 1);
        float nr16 = (float)(min(i + 8, 223) - max(i - 7, 0) + 1);
        s_tab[i] = make_float4(EPS_ - nr2 * nc2 * mi,  EPS_ - nr4 * nc4 * mi,
                               EPS_ - nr8 * nc8 * mi,  EPS_ - nr16 * nc16 * mi);
    }
    __syncthreads();

    const size_t bh2 = (size_t)b * H_ * ST2;
    const size_t bh8 = (size_t)b * H_ * ST8;
    const float* p2   = g_H2 + bh2 + (j + 1) * C_ + c;
    const float* p4a  = g_H2 + bh2 + (j    ) * C_ + c;
    const float* p4b  = g_H2 + bh2 + (j + 2) * C_ + c;
    const float* p8   = g_H8 + bh8 + (j + 4) * C_ + c;
    const float* p16a = g_H8 + bh8 + (j    ) * C_ + c;
    const float* p16b = g_H8 + bh8 + (j + 8) * C_ + c;
    const float* xr   = x   + ((size_t)b * H_ * W_ + j) * C_ + c;
    float*       orr  = out + ((size_t)b * H_ * W_ + j) * C_ + c;

    float r2[2], r4[4], r8[8], r16[16];

    #pragma unroll
    for (int d = -7; d <= 7; d++) {
        const int t = i0 + d;
        const bool v = (t >= 0);
        r16[d + 7] = v ? (p16a[t * ST8] + p16b[t * ST8]) : 0.f;
        if (d >= -3 && d <= 3) r8[d + 3] = v ? p8[t * ST8] : 0.f;
        if (d >= -1 && d <= 1) r4[d + 1] = v ? (p4a[t * ST2] + p4b[t * ST2]) : 0.f;
        if (d == 0)            r2[0]     = v ? p2[t * ST2] : 0.f;
    }

    for (int base = 0; base < CH_; base += 16) {
        #pragma unroll
        for (int u = 0; u < 16; u++) {
            if (base + u >= CH_) break;
            const int i = i0 + base + u;
            const int t16 = i + 8, t8 = i + 4, t4 = i + 2, t2 = i + 1;
            r16[(15 + u) & 15] = (t16 < H_) ? (p16a[t16 * ST8] + p16b[t16 * ST8]) : 0.f;
            r8 [(7 + u) & 7]   = (t8  < H_) ? p8[t8 * ST8] : 0.f;
            r4 [(3 + u) & 3]   = (t4  < H_) ? (p4a[t4 * ST2] + p4b[t4 * ST2]) : 0.f;
            r2 [(1 + u) & 1]   = (t2  < H_) ? p2[t2 * ST2] : 0.f;

            const float m2 = r2[0] + r2[1];
            const float m4 = (r4[0] + r4[1]) + (r4[2] + r4[3]);
            const float m8 = ((r8[0] + r8[1]) + (r8[2] + r8[3]))
                           + ((r8[4] + r8[5]) + (r8[6] + r8[7]));
            const float m16 = (((r16[0] + r16[1]) + (r16[2] + r16[3]))
                            +  ((r16[4] + r16[5]) + (r16[6] + r16[7])))
                            + (((r16[8] + r16[9]) + (r16[10] + r16[11]))
                            +  ((r16[12] + r16[13]) + (r16[14] + r16[15])));

            const float4 tb = s_tab[i];
            const float ly0 = __logf(fmaf(m2,  inv, tb.x));
            const float ly1 = __logf(fmaf(m4,  inv, tb.y));
            const float ly2 = __logf(fmaf(m8,  inv, tb.z));
            const float ly3 = __logf(fmaf(m16, inv, tb.w));
            const float alpha = fmaf(c3, ly3, fmaf(c2, ly2, fmaf(c1, ly1, c0 * ly0)));
            const float a = fmaf(alpha, bsc, bsh);

            float cnt = 0.f;
            #pragma unroll
            for (int k = 0; k < K_; k++) {
                float h = fmaf(-wd[k], fabsf(a - an[k]), 1.f);
                cnt += fmaxf(h, 0.f);
            }
            const float sig = __fdividef(1.f, 1.f + __expf(-cnt));
            orr[i * STX] = xr[i * STX] + sig;
        }
    }
}

extern "C" void kernel_launch(void* const* d_in, const int* in_sizes, int n_in,
                              void* d_out, int out_size) {
    const float* x    = (const float*)d_in[0];
    const float* olsw = (const float*)d_in[1];
    const float* anch = (const float*)d_in[2];
    const float* wdth = (const float*)d_in[3];
    const float* gmm  = (const float*)d_in[4];
    const float* bta  = (const float*)d_in[5];
    const float* mea  = (const float*)d_in[6];
    const float* vrr  = (const float*)d_in[7];
    float* out = (float*)d_out;

    kA<<<dim3(H_, B_), dim3(C_, 4)>>>(x);
    kB<<<dim3(W_, H_ / CH_, B_), C_>>>(x, olsw, anch, wdth, gmm, bta, mea, vrr, out);
}

// round 10
// speedup vs baseline: 1.6985x; 1.4976x over previous
#include <cuda_runtime.h>
#include <cuda_bf16.h>

#define B_ 4
#define H_ 224
#define W_ 224
#define C_ 64
#define K_ 8
#define EPS_ 1e-6f

#define H2_W 226            // H2 idx s: window cols [s-1, s] zero-padded
#define H8_W 232            // H8 idx u: window cols [u-7, u] zero-padded
#define ST2 (H2_W * C_)
#define ST8 (H8_W * C_)
#define STX (W_ * C_)
#define CH_ 56              // rows per kB chunk (4 chunks)

__device__ float g_H2[(size_t)B_ * H_ * H2_W * C_];
__device__ float g_H8[(size_t)B_ * H_ * H8_W * C_];
__device__ float g_rmn[B_ * H_], g_rmx[B_ * H_];

// One-pass streaming front-end: per-row min/max + H2 + H8 (RAW sums).
__global__ void __launch_bounds__(256) kA(const float* __restrict__ x) {
    const int c = threadIdx.x;                  // 0..63
    const int seg = threadIdx.y;                // 0..3
    const int t = blockIdx.x;                   // row
    const int b = blockIdx.y;

    const float* xr  = x    + (((size_t)b * H_ + t) * W_  ) * C_ + c;
    float*       h2g = g_H2 + (((size_t)b * H_ + t) * H2_W) * C_ + c;
    float*       h8g = g_H8 + (((size_t)b * H_ + t) * H8_W) * C_ + c;

    const int u0  = seg * 64;
    const int len = (seg == 3) ? (H8_W - 192) : 64;    // 40 : 64

    float mn = 3.402823466e38f, mx = -3.402823466e38f;
    float ring[8];
    #pragma unroll
    for (int i = 0; i < 8; i++) ring[i] = 0.f;

    float xprev;
    {
        int up = u0 - 8;
        float xp = (up >= 0 && up <= 223) ? xr[up * C_] : 0.f;
        #pragma unroll
        for (int d = -7; d <= -1; d++) {
            const int u = u0 + d;
            float xc = (u >= 0 && u <= 223) ? xr[u * C_] : 0.f;
            ring[(d + 8) & 7] = xp + xc;
            xp = xc;
        }
        xprev = xp;
    }

    for (int base = 0; base < len; base += 8) {
        #pragma unroll
        for (int vv = 0; vv < 8; vv++) {
            const int v = base + vv;
            const int u = u0 + v;
            float xc = 0.f;
            if (u <= 223) {
                xc = xr[u * C_];
                mn = fminf(mn, xc);
                mx = fmaxf(mx, xc);
            }
            const float h2 = xprev + xc;
            xprev = xc;
            ring[v & 7] = h2;
            const float h8 = (h2 + ring[(v - 2) & 7])
                           + (ring[(v - 4) & 7] + ring[(v - 6) & 7]);
            if (u <= 225) h2g[u * C_] = h2;
            h8g[u * C_] = h8;
        }
    }

    #pragma unroll
    for (int o = 16; o; o >>= 1) {
        mn = fminf(mn, __shfl_xor_sync(0xffffffffu, mn, o));
        mx = fmaxf(mx, __shfl_xor_sync(0xffffffffu, mx, o));
    }
    __shared__ float smn[8], smx[8];
    const int tid = threadIdx.y * 64 + threadIdx.x;
    if ((tid & 31) == 0) { smn[tid >> 5] = mn; smx[tid >> 5] = mx; }
    __syncthreads();
    if (tid == 0) {
        #pragma unroll
        for (int i = 1; i < 8; i++) { mn = fminf(mn, smn[i]); mx = fmaxf(mx, smx[i]); }
        g_rmn[b * H_ + t] = mn;
        g_rmx[b * H_ + t] = mx;
    }
}

__global__ void __launch_bounds__(64, 12) kB(
    const float* __restrict__ x,    const float* __restrict__ olsw,
    const float* __restrict__ anch, const float* __restrict__ wdth,
    const float* __restrict__ gmm,  const float* __restrict__ bta,
    const float* __restrict__ mea,  const float* __restrict__ vrr,
    float* __restrict__ out)
{
    const int c = threadIdx.x;
    const int j = blockIdx.x;
    const int i0 = blockIdx.y * CH_;
    const int b = blockIdx.z;

    // reduce per-row min/max -> sample min/max
    float mn = 3.402823466e38f, mx = -3.402823466e38f;
    for (int i = c; i < H_; i += 64) {
        mn = fminf(mn, g_rmn[b * H_ + i]);
        mx = fmaxf(mx, g_rmx[b * H_ + i]);
    }
    #pragma unroll
    for (int o = 16; o; o >>= 1) {
        mn = fminf(mn, __shfl_xor_sync(0xffffffffu, mn, o));
        mx = fmaxf(mx, __shfl_xor_sync(0xffffffffu, mx, o));
    }
    __shared__ float sred[4];
    if ((c & 31) == 0) { sred[(c >> 5)] = mn; sred[(c >> 5) + 2] = mx; }
    __syncthreads();
    mn = fminf(sred[0], sred[1]);
    mx = fmaxf(sred[2], sred[3]);

    const float w0 = olsw[0], w1 = olsw[1], w2 = olsw[2], w3 = olsw[3];
    const float L1 = 0.69314718f, L2 = 1.38629436f, L3 = 2.07944154f, L4 = 2.77258872f;
    const float wsum = w0 + w1 + w2 + w3;
    const float lrb = (w0 * L1 + w1 * L2 + w2 * L3 + w3 * L4) / wsum;
    const float d0 = L1 - lrb, d1 = L2 - lrb, d2 = L3 - lrb, d3 = L4 - lrb;
    const float den = w0 * d0 * d0 + w1 * d1 * d1 + w2 * d2 * d2 + w3 * d3 * d3;
    const float ivd = 1.f / den;
    const float c0 = w0 * d0 * ivd, c1 = w1 * d1 * ivd, c2 = w2 * d2 * ivd, c3 = w3 * d3 * ivd;

    const float bsc = gmm[c] * rsqrtf(vrr[c] + 1e-3f);
    const float bsh = bta[c] - mea[c] * bsc;

    // anchors/widths in smem (frees 16 regs)
    __shared__ float2 s_aw[K_ * C_];
    #pragma unroll
    for (int k = 0; k < K_; k++)
        s_aw[k * C_ + c] = make_float2(anch[c * K_ + k], wdth[c * K_ + k]);

    // scaling: m + eps = fma(rawsum, inv, eps - n*mn*inv)
    const float inv = 1.f / (mx - mn + EPS_);
    const float mi  = mn * inv;
    const float nc2  = (float)(min(j + 1, 223) - j + 1);
    const float nc4  = (float)(min(j + 2, 223) - max(j - 1, 0) + 1);
    const float nc8  = (float)(min(j + 4, 223) - max(j - 3, 0) + 1);
    const float nc16 = (float)(min(j + 8, 223) - max(j - 7, 0) + 1);

    __shared__ float4 s_tab[H_];
    for (int i = c; i < H_; i += 64) {
        float nr2  = (float)(min(i + 1, 223) - i + 1);
        float nr4  = (float)(min(i + 2, 223) - max(i - 1, 0) + 1);
        float nr8  = (float)(min(i + 4, 223) - max(i - 3, 0) + 1);
        float nr16 = (float)(min(i + 8, 223) - max(i - 7, 0) + 1);
        s_tab[i] = make_float4(EPS_ - nr2 * nc2 * mi,  EPS_ - nr4 * nc4 * mi,
                               EPS_ - nr8 * nc8 * mi,  EPS_ - nr16 * nc16 * mi);
    }
    __syncthreads();

    const size_t bh2 = (size_t)b * H_ * ST2;
    const size_t bh8 = (size_t)b * H_ * ST8;
    const float* p2   = g_H2 + bh2 + (j + 1) * C_ + c;
    const float* p4a  = g_H2 + bh2 + (j    ) * C_ + c;
    const float* p4b  = g_H2 + bh2 + (j + 2) * C_ + c;
    const float* p8   = g_H8 + bh8 + (j + 4) * C_ + c;
    const float* p16a = g_H8 + bh8 + (j    ) * C_ + c;
    const float* p16b = g_H8 + bh8 + (j + 8) * C_ + c;
    const float* xr   = x   + ((size_t)b * H_ * W_ + j) * C_ + c;
    float*       orr  = out + ((size_t)b * H_ * W_ + j) * C_ + c;

    float r2[2], r4[4], r8[8], r16[16];

    // prefill: branch-free clamped loads * validity
    #pragma unroll
    for (int d = -7; d <= 7; d++) {
        const int t = i0 + d;
        const int tc = t < 0 ? 0 : t;             // upper bound safe (<=175)
        const float vf = t < 0 ? 0.f : 1.f;
        r16[d + 7] = vf * (p16a[tc * ST8] + p16b[tc * ST8]);
        if (d >= -3 && d <= 3) r8[d + 3] = vf * p8[tc * ST8];
        if (d >= -1 && d <= 1) r4[d + 1] = vf * (p4a[tc * ST2] + p4b[tc * ST2]);
        if (d == 0)            r2[0]     = vf * p2[tc * ST2];
    }

    for (int base = 0; base < CH_; base += 16) {
        #pragma unroll
        for (int u = 0; u < 16; u++) {
            if (base + u >= CH_) break;
            const int i = i0 + base + u;
            const int t16 = i + 8, t8 = i + 4, t4 = i + 2, t2 = i + 1;
            const int a16 = min(t16, 223), a8 = min(t8, 223);
            const int a4  = min(t4, 223),  a2 = min(t2, 223);
            const float v16 = (t16 <= 223) ? 1.f : 0.f;
            const float v8  = (t8  <= 223) ? 1.f : 0.f;
            const float v4  = (t4  <= 223) ? 1.f : 0.f;
            const float v2  = (t2  <= 223) ? 1.f : 0.f;
            r16[(15 + u) & 15] = v16 * (p16a[a16 * ST8] + p16b[a16 * ST8]);
            r8 [(7 + u) & 7]   = v8  * p8[a8 * ST8];
            r4 [(3 + u) & 3]   = v4  * (p4a[a4 * ST2] + p4b[a4 * ST2]);
            r2 [(1 + u) & 1]   = v2  * p2[a2 * ST2];

            const float m2 = r2[0] + r2[1];
            const float m4 = (r4[0] + r4[1]) + (r4[2] + r4[3]);
            const float m8 = ((r8[0] + r8[1]) + (r8[2] + r8[3]))
                           + ((r8[4] + r8[5]) + (r8[6] + r8[7]));
            const float m16 = (((r16[0] + r16[1]) + (r16[2] + r16[3]))
                            +  ((r16[4] + r16[5]) + (r16[6] + r16[7])))
                            + (((r16[8] + r16[9]) + (r16[10] + r16[11]))
                            +  ((r16[12] + r16[13]) + (r16[14] + r16[15])));

            const float4 tb = s_tab[i];
            const float ly0 = __logf(fmaf(m2,  inv, tb.x));
            const float ly1 = __logf(fmaf(m4,  inv, tb.y));
            const float ly2 = __logf(fmaf(m8,  inv, tb.z));
            const float ly3 = __logf(fmaf(m16, inv, tb.w));
            const float alpha = fmaf(c3, ly3, fmaf(c2, ly2, fmaf(c1, ly1, c0 * ly0)));
            const float a = fmaf(alpha, bsc, bsh);

            float cnt = 0.f;
            #pragma unroll
            for (int k = 0; k < K_; k++) {
                const float2 aw = s_aw[k * C_ + c];
                float h = fmaf(-aw.y, fabsf(a - aw.x), 1.f);
                cnt += fmaxf(h, 0.f);
            }
            const float sig = __fdividef(1.f, 1.f + __expf(-cnt));
            orr[i * STX] = xr[i * STX] + sig;
        }
    }
}

extern "C" void kernel_launch(void* const* d_in, const int* in_sizes, int n_in,
                              void* d_out, int out_size) {
    const float* x    = (const float*)d_in[0];
    const float* olsw = (const float*)d_in[1];
    const float* anch = (const float*)d_in[2];
    const float* wdth = (const float*)d_in[3];
    const float* gmm  = (const float*)d_in[4];
    const float* bta  = (const float*)d_in[5];
    const float* mea  = (const float*)d_in[6];
    const float* vrr  = (const float*)d_in[7];
    float* out = (float*)d_out;

    kA<<<dim3(H_, B_), dim3(C_, 4)>>>(x);
    kB<<<dim3(W_, H_ / CH_, B_), C_>>>(x, olsw, anch, wdth, gmm, bta, mea, vrr, out);
}

// round 11
// speedup vs baseline: 1.7584x; 1.0352x over previous
#include <cuda_runtime.h>
#include <cuda_bf16.h>

#define B_ 4
#define H_ 224
#define W_ 224
#define C_ 64
#define K_ 8
#define EPS_ 1e-6f

#define H2_W 226
#define H8_W 232
#define ST2 (H2_W * C_)
#define ST8 (H8_W * C_)
#define STX (W_ * C_)
#define CH_ 56              // rows per kB chunk (even; 4 chunks)

__device__ float g_H2[(size_t)B_ * H_ * H2_W * C_];
__device__ float g_H8[(size_t)B_ * H_ * H8_W * C_];
__device__ float g_rmn[B_ * H_], g_rmx[B_ * H_];

// One-pass streaming front-end: per-row min/max + H2 + H8 (RAW sums).
__global__ void __launch_bounds__(256) kA(const float* __restrict__ x) {
    const int c = threadIdx.x;
    const int seg = threadIdx.y;
    const int t = blockIdx.x;
    const int b = blockIdx.y;

    const float* xr  = x    + (((size_t)b * H_ + t) * W_  ) * C_ + c;
    float*       h2g = g_H2 + (((size_t)b * H_ + t) * H2_W) * C_ + c;
    float*       h8g = g_H8 + (((size_t)b * H_ + t) * H8_W) * C_ + c;

    const int u0  = seg * 64;
    const int len = (seg == 3) ? (H8_W - 192) : 64;

    float mn = 3.402823466e38f, mx = -3.402823466e38f;
    float ring[8];
    #pragma unroll
    for (int i = 0; i < 8; i++) ring[i] = 0.f;

    float xprev;
    {
        int up = u0 - 8;
        float xp = (up >= 0 && up <= 223) ? xr[up * C_] : 0.f;
        #pragma unroll
        for (int d = -7; d <= -1; d++) {
            const int u = u0 + d;
            float xc = (u >= 0 && u <= 223) ? xr[u * C_] : 0.f;
            ring[(d + 8) & 7] = xp + xc;
            xp = xc;
        }
        xprev = xp;
    }

    for (int base = 0; base < len; base += 8) {
        #pragma unroll
        for (int vv = 0; vv < 8; vv++) {
            const int v = base + vv;
            const int u = u0 + v;
            float xc = 0.f;
            if (u <= 223) {
                xc = xr[u * C_];
                mn = fminf(mn, xc);
                mx = fmaxf(mx, xc);
            }
            const float h2 = xprev + xc;
            xprev = xc;
            ring[v & 7] = h2;
            const float h8 = (h2 + ring[(v - 2) & 7])
                           + (ring[(v - 4) & 7] + ring[(v - 6) & 7]);
            if (u <= 225) h2g[u * C_] = h2;
            h8g[u * C_] = h8;
        }
    }

    #pragma unroll
    for (int o = 16; o; o >>= 1) {
        mn = fminf(mn, __shfl_xor_sync(0xffffffffu, mn, o));
        mx = fmaxf(mx, __shfl_xor_sync(0xffffffffu, mx, o));
    }
    __shared__ float smn[8], smx[8];
    const int tid = threadIdx.y * 64 + threadIdx.x;
    if ((tid & 31) == 0) { smn[tid >> 5] = mn; smx[tid >> 5] = mx; }
    __syncthreads();
    if (tid == 0) {
        #pragma unroll
        for (int i = 1; i < 8; i++) { mn = fminf(mn, smn[i]); mx = fmaxf(mx, smx[i]); }
        g_rmn[b * H_ + t] = mn;
        g_rmx[b * H_ + t] = mx;
    }
}

struct TailC { float inv, c0, c1, c2, c3, bsc, bsh; };

static __device__ __forceinline__ float tail_sig(
    float m2, float m4, float m8, float m16, float4 tb,
    const TailC& tc, const float2* s_aw, int c)
{
    const float ly0 = __logf(fmaf(m2,  tc.inv, tb.x));
    const float ly1 = __logf(fmaf(m4,  tc.inv, tb.y));
    const float ly2 = __logf(fmaf(m8,  tc.inv, tb.z));
    const float ly3 = __logf(fmaf(m16, tc.inv, tb.w));
    const float alpha = fmaf(tc.c3, ly3, fmaf(tc.c2, ly2, fmaf(tc.c1, ly1, tc.c0 * ly0)));
    const float a = fmaf(alpha, tc.bsc, tc.bsh);
    float cnt = 0.f;
    #pragma unroll
    for (int k = 0; k < K_; k++) {
        const float2 aw = s_aw[k * C_ + c];
        float h = fmaf(-aw.y, fabsf(a - aw.x), 1.f);
        cnt += fmaxf(h, 0.f);
    }
    return __fdividef(1.f, 1.f + __expf(-cnt));
}

__global__ void __launch_bounds__(64, 16) kB(
    const float* __restrict__ x,    const float* __restrict__ olsw,
    const float* __restrict__ anch, const float* __restrict__ wdth,
    const float* __restrict__ gmm,  const float* __restrict__ bta,
    const float* __restrict__ mea,  const float* __restrict__ vrr,
    float* __restrict__ out)
{
    const int c = threadIdx.x;
    const int j = blockIdx.x;
    const int i0 = blockIdx.y * CH_;
    const int b = blockIdx.z;

    float mn = 3.402823466e38f, mx = -3.402823466e38f;
    for (int i = c; i < H_; i += 64) {
        mn = fminf(mn, g_rmn[b * H_ + i]);
        mx = fmaxf(mx, g_rmx[b * H_ + i]);
    }
    #pragma unroll
    for (int o = 16; o; o >>= 1) {
        mn = fminf(mn, __shfl_xor_sync(0xffffffffu, mn, o));
        mx = fmaxf(mx, __shfl_xor_sync(0xffffffffu, mx, o));
    }
    __shared__ float sred[4];
    if ((c & 31) == 0) { sred[(c >> 5)] = mn; sred[(c >> 5) + 2] = mx; }
    __syncthreads();
    mn = fminf(sred[0], sred[1]);
    mx = fmaxf(sred[2], sred[3]);

    const float w0 = olsw[0], w1 = olsw[1], w2 = olsw[2], w3 = olsw[3];
    const float L1 = 0.69314718f, L2 = 1.38629436f, L3 = 2.07944154f, L4 = 2.77258872f;
    const float wsum = w0 + w1 + w2 + w3;
    const float lrb = (w0 * L1 + w1 * L2 + w2 * L3 + w3 * L4) / wsum;
    const float d0 = L1 - lrb, d1 = L2 - lrb, d2 = L3 - lrb, d3 = L4 - lrb;
    const float den = w0 * d0 * d0 + w1 * d1 * d1 + w2 * d2 * d2 + w3 * d3 * d3;
    const float ivd = 1.f / den;

    TailC tc;
    tc.inv = 1.f / (mx - mn + EPS_);
    tc.c0 = w0 * d0 * ivd; tc.c1 = w1 * d1 * ivd;
    tc.c2 = w2 * d2 * ivd; tc.c3 = w3 * d3 * ivd;
    tc.bsc = gmm[c] * rsqrtf(vrr[c] + 1e-3f);
    tc.bsh = bta[c] - mea[c] * tc.bsc;

    __shared__ float2 s_aw[K_ * C_];
    #pragma unroll
    for (int k = 0; k < K_; k++)
        s_aw[k * C_ + c] = make_float2(anch[c * K_ + k], wdth[c * K_ + k]);

    const float mi  = mn * tc.inv;
    const float nc2  = (float)(min(j + 1, 223) - j + 1);
    const float nc4  = (float)(min(j + 2, 223) - max(j - 1, 0) + 1);
    const float nc8  = (float)(min(j + 4, 223) - max(j - 3, 0) + 1);
    const float nc16 = (float)(min(j + 8, 223) - max(j - 7, 0) + 1);

    __shared__ float4 s_tab[H_];
    for (int i = c; i < H_; i += 64) {
        float nr2  = (float)(min(i + 1, 223) - i + 1);
        float nr4  = (float)(min(i + 2, 223) - max(i - 1, 0) + 1);
        float nr8  = (float)(min(i + 4, 223) - max(i - 3, 0) + 1);
        float nr16 = (float)(min(i + 8, 223) - max(i - 7, 0) + 1);
        s_tab[i] = make_float4(EPS_ - nr2 * nc2 * mi,  EPS_ - nr4 * nc4 * mi,
                               EPS_ - nr8 * nc8 * mi,  EPS_ - nr16 * nc16 * mi);
    }
    __syncthreads();

    const size_t bh2 = (size_t)b * H_ * ST2;
    const size_t bh8 = (size_t)b * H_ * ST8;
    const float* p2   = g_H2 + bh2 + (j + 1) * C_ + c;
    const float* p4a  = g_H2 + bh2 + (j    ) * C_ + c;
    const float* p4b  = g_H2 + bh2 + (j + 2) * C_ + c;
    const float* p8   = g_H8 + bh8 + (j + 4) * C_ + c;
    const float* p16a = g_H8 + bh8 + (j    ) * C_ + c;
    const float* p16b = g_H8 + bh8 + (j + 8) * C_ + c;
    const float* xr   = x   + ((size_t)b * H_ * W_ + j) * C_ + c;
    float*       orr  = out + ((size_t)b * H_ * W_ + j) * C_ + c;

    float r2[2], r4[4], r8[8], r16[16];

    // prefill: relative row r in [-8..7] -> slot (r+7)&mask; fill r=-7..7
    #pragma unroll
    for (int d = -7; d <= 7; d++) {
        const int t = i0 + d;
        const int tcl = t < 0 ? 0 : t;
        const float vf = t < 0 ? 0.f : 1.f;
        r16[d + 7] = vf * (p16a[tcl * ST8] + p16b[tcl * ST8]);
        if (d >= -3 && d <= 3) r8[d + 3] = vf * p8[tcl * ST8];
        if (d >= -1 && d <= 1) r4[d + 1] = vf * (p4a[tcl * ST2] + p4b[tcl * ST2]);
        if (d == 0)            r2[0]     = vf * p2[tcl * ST2];
    }

    for (int base = 0; base < CH_; base += 16) {
        #pragma unroll
        for (int p = 0; p < 8; p++) {
            const int u = 2 * p;                 // relative phase (base mult of 16)
            if (base + u >= CH_) break;
            const int i = i0 + base + u;

            // ---- insert first new rows (i+8 / i+4 / i+2 / i+1) ----
            {
                const int t = i + 8; const int a = min(t, 223);
                const float v = (t <= 223) ? 1.f : 0.f;
                r16[(u + 15) & 15] = v * (p16a[a * ST8] + p16b[a * ST8]);
            }
            {
                const int t = i + 4; const int a = min(t, 223);
                const float v = (t <= 223) ? 1.f : 0.f;
                r8[(u + 7) & 7] = v * p8[a * ST8];
            }
            {
                const int t = i + 2; const int a = min(t, 223);
                const float v = (t <= 223) ? 1.f : 0.f;
                r4[(u + 3) & 3] = v * (p4a[a * ST2] + p4b[a * ST2]);
            }
            {
                const int t = i + 1; const int a = min(t, 223);
                const float v = (t <= 223) ? 1.f : 0.f;
                r2[(u + 1) & 1] = v * p2[a * ST2];
            }

            // ---- shared cores (excluded slot folded as +0.f) ----
            #define Z16(s) (((s) == (u & 15)) ? 0.f : r16[s])
            const float A16 =
                ((((Z16(0)+Z16(1))+(Z16(2)+Z16(3)))+((Z16(4)+Z16(5))+(Z16(6)+Z16(7))))
               + (((Z16(8)+Z16(9))+(Z16(10)+Z16(11)))+((Z16(12)+Z16(13))+(Z16(14)+Z16(15)))));
            #undef Z16
            #define Z8(s) (((s) == (u & 7)) ? 0.f : r8[s])
            const float A8 = ((Z8(0)+Z8(1))+(Z8(2)+Z8(3)))+((Z8(4)+Z8(5))+(Z8(6)+Z8(7)));
            #undef Z8
            #define Z4(s) (((s) == (u & 3)) ? 0.f : r4[s])
            const float A4 = (Z4(0)+Z4(1))+(Z4(2)+Z4(3));
            #undef Z4

            const float m16_0 = A16 + r16[u & 15];
            const float m8_0  = A8  + r8[u & 7];
            const float m4_0  = A4  + r4[u & 3];
            const float m2_0  = r2[0] + r2[1];

            // ---- insert second new rows (i+9 / i+5 / i+3 / i+2) into freed slots ----
            {
                const int t = i + 9; const int a = min(t, 223);
                const float v = (t <= 223) ? 1.f : 0.f;
                r16[u & 15] = v * (p16a[a * ST8] + p16b[a * ST8]);
            }
            {
                const int t = i + 5; const int a = min(t, 223);
                const float v = (t <= 223) ? 1.f : 0.f;
                r8[u & 7] = v * p8[a * ST8];
            }
            {
                const int t = i + 3; const int a = min(t, 223);
                const float v = (t <= 223) ? 1.f : 0.f;
                r4[u & 3] = v * (p4a[a * ST2] + p4b[a * ST2]);
            }
            {
                const int t = i + 2; const int a = min(t, 223);
                const float v = (t <= 223) ? 1.f : 0.f;
                r2[u & 1] = v * p2[a * ST2];
            }

            const float m16_1 = A16 + r16[u & 15];
            const float m8_1  = A8  + r8[u & 7];
            const float m4_1  = A4  + r4[u & 3];
            const float m2_1  = r2[(u + 1) & 1] + r2[u & 1];

            const float sig0 = tail_sig(m2_0, m4_0, m8_0, m16_0, s_tab[i],     tc, s_aw, c);
            const float sig1 = tail_sig(m2_1, m4_1, m8_1, m16_1, s_tab[i + 1], tc, s_aw, c);
            orr[i * STX]       = xr[i * STX]       + sig0;
            orr[(i + 1) * STX] = xr[(i + 1) * STX] + sig1;
        }
    }
}

extern "C" void kernel_launch(void* const* d_in, const int* in_sizes, int n_in,
                              void* d_out, int out_size) {
    const float* x    = (const float*)d_in[0];
    const float* olsw = (const float*)d_in[1];
    const float* anch = (const float*)d_in[2];
    const float* wdth = (const float*)d_in[3];
    const float* gmm  = (const float*)d_in[4];
    const float* bta  = (const float*)d_in[5];
    const float* mea  = (const float*)d_in[6];
    const float* vrr  = (const float*)d_in[7];
    float* out = (float*)d_out;

    kA<<<dim3(H_, B_), dim3(C_, 4)>>>(x);
    kB<<<dim3(W_, H_ / CH_, B_), C_>>>(x, olsw, anch, wdth, gmm, bta, mea, vrr, out);
}

// round 12
// speedup vs baseline: 2.2053x; 1.2542x over previous
#include <cuda_runtime.h>
#include <cuda_bf16.h>

#define B_ 4
#define H_ 224
#define W_ 224
#define C_ 64
#define K_ 8
#define EPS_ 1e-6f

#define H2_W 226
#define H8_W 232
#define ST2 (H2_W * C_)
#define ST8 (H8_W * C_)
#define STX (W_ * C_)
#define RT_ 242             // 8 pad + 224 + 10 pad rows (pads stay zero forever)
#define CH_ 28              // rows per kB chunk (8 chunks -> 3.03 waves)

__device__ float g_H2[(size_t)B_ * RT_ * ST2];
__device__ float g_H8[(size_t)B_ * RT_ * ST8];
__device__ float g_rmn[B_ * H_], g_rmx[B_ * H_];

// One-pass streaming front-end: per-row min/max + H2 + H8 (RAW sums).
// Writes real rows at +8 offset; pad rows are never touched (stay zero).
__global__ void __launch_bounds__(256) kA(const float* __restrict__ x) {
    const int c = threadIdx.x;
    const int seg = threadIdx.y;
    const int t = blockIdx.x;
    const int b = blockIdx.y;

    const float* xr  = x    + (((size_t)b * H_ + t) * W_) * C_ + c;
    float*       h2g = g_H2 + ((size_t)b * RT_ + 8 + t) * ST2 + c;
    float*       h8g = g_H8 + ((size_t)b * RT_ + 8 + t) * ST8 + c;

    const int u0  = seg * 64;
    const int len = (seg == 3) ? (H8_W - 192) : 64;

    float mn = 3.402823466e38f, mx = -3.402823466e38f;
    float ring[8];
    #pragma unroll
    for (int i = 0; i < 8; i++) ring[i] = 0.f;

    float xprev;
    {
        int up = u0 - 8;
        float xp = (up >= 0 && up <= 223) ? xr[up * C_] : 0.f;
        #pragma unroll
        for (int d = -7; d <= -1; d++) {
            const int u = u0 + d;
            float xc = (u >= 0 && u <= 223) ? xr[u * C_] : 0.f;
            ring[(d + 8) & 7] = xp + xc;
            xp = xc;
        }
        xprev = xp;
    }

    for (int base = 0; base < len; base += 8) {
        #pragma unroll
        for (int vv = 0; vv < 8; vv++) {
            const int v = base + vv;
            const int u = u0 + v;
            float xc = 0.f;
            if (u <= 223) {
                xc = xr[u * C_];
                mn = fminf(mn, xc);
                mx = fmaxf(mx, xc);
            }
            const float h2 = xprev + xc;
            xprev = xc;
            ring[v & 7] = h2;
            const float h8 = (h2 + ring[(v - 2) & 7])
                           + (ring[(v - 4) & 7] + ring[(v - 6) & 7]);
            if (u <= 225) h2g[u * C_] = h2;
            h8g[u * C_] = h8;
        }
    }

    #pragma unroll
    for (int o = 16; o; o >>= 1) {
        mn = fminf(mn, __shfl_xor_sync(0xffffffffu, mn, o));
        mx = fmaxf(mx, __shfl_xor_sync(0xffffffffu, mx, o));
    }
    __shared__ float smn[8], smx[8];
    const int tid = threadIdx.y * 64 + threadIdx.x;
    if ((tid & 31) == 0) { smn[tid >> 5] = mn; smx[tid >> 5] = mx; }
    __syncthreads();
    if (tid == 0) {
        #pragma unroll
        for (int i = 1; i < 8; i++) { mn = fminf(mn, smn[i]); mx = fmaxf(mx, smx[i]); }
        g_rmn[b * H_ + t] = mn;
        g_rmx[b * H_ + t] = mx;
    }
}

struct TailC { float inv, c0, c1, c2, c3, bsc, bsh; };

static __device__ __forceinline__ float tail_sig(
    float m2, float m4, float m8, float m16, float4 tb,
    const TailC& tc, const float2* s_aw, int c)
{
    const float ly0 = __logf(fmaf(m2,  tc.inv, tb.x));
    const float ly1 = __logf(fmaf(m4,  tc.inv, tb.y));
    const float ly2 = __logf(fmaf(m8,  tc.inv, tb.z));
    const float ly3 = __logf(fmaf(m16, tc.inv, tb.w));
    const float alpha = fmaf(tc.c3, ly3, fmaf(tc.c2, ly2, fmaf(tc.c1, ly1, tc.c0 * ly0)));
    const float a = fmaf(alpha, tc.bsc, tc.bsh);
    float cnt = 0.f;
    #pragma unroll
    for (int k = 0; k < K_; k++) {
        const float2 aw = s_aw[k * C_ + c];
        float h = fmaf(-aw.y, fabsf(a - aw.x), 1.f);
        cnt += fmaxf(h, 0.f);
    }
    return __fdividef(1.f, 1.f + __expf(-cnt));
}

__global__ void __launch_bounds__(64, 16) kB(
    const float* __restrict__ x,    const float* __restrict__ olsw,
    const float* __restrict__ anch, const float* __restrict__ wdth,
    const float* __restrict__ gmm,  const float* __restrict__ bta,
    const float* __restrict__ mea,  const float* __restrict__ vrr,
    float* __restrict__ out)
{
    const int c = threadIdx.x;
    const int j = blockIdx.x;
    const int i0 = blockIdx.y * CH_;
    const int b = blockIdx.z;

    float mn = 3.402823466e38f, mx = -3.402823466e38f;
    for (int i = c; i < H_; i += 64) {
        mn = fminf(mn, g_rmn[b * H_ + i]);
        mx = fmaxf(mx, g_rmx[b * H_ + i]);
    }
    #pragma unroll
    for (int o = 16; o; o >>= 1) {
        mn = fminf(mn, __shfl_xor_sync(0xffffffffu, mn, o));
        mx = fmaxf(mx, __shfl_xor_sync(0xffffffffu, mx, o));
    }
    __shared__ float sred[4];
    if ((c & 31) == 0) { sred[(c >> 5)] = mn; sred[(c >> 5) + 2] = mx; }
    __syncthreads();
    mn = fminf(sred[0], sred[1]);
    mx = fmaxf(sred[2], sred[3]);

    const float w0 = olsw[0], w1 = olsw[1], w2 = olsw[2], w3 = olsw[3];
    const float L1 = 0.69314718f, L2 = 1.38629436f, L3 = 2.07944154f, L4 = 2.77258872f;
    const float wsum = w0 + w1 + w2 + w3;
    const float lrb = (w0 * L1 + w1 * L2 + w2 * L3 + w3 * L4) / wsum;
    const float d0 = L1 - lrb, d1 = L2 - lrb, d2 = L3 - lrb, d3 = L4 - lrb;
    const float den = w0 * d0 * d0 + w1 * d1 * d1 + w2 * d2 * d2 + w3 * d3 * d3;
    const float ivd = 1.f / den;

    TailC tc;
    tc.inv = 1.f / (mx - mn + EPS_);
    tc.c0 = w0 * d0 * ivd; tc.c1 = w1 * d1 * ivd;
    tc.c2 = w2 * d2 * ivd; tc.c3 = w3 * d3 * ivd;
    tc.bsc = gmm[c] * rsqrtf(vrr[c] + 1e-3f);
    tc.bsh = bta[c] - mea[c] * tc.bsc;

    __shared__ float2 s_aw[K_ * C_];
    #pragma unroll
    for (int k = 0; k < K_; k++)
        s_aw[k * C_ + c] = make_float2(anch[c * K_ + k], wdth[c * K_ + k]);

    const float mi  = mn * tc.inv;
    const float nc2  = (float)(min(j + 1, 223) - j + 1);
    const float nc4  = (float)(min(j + 2, 223) - max(j - 1, 0) + 1);
    const float nc8  = (float)(min(j + 4, 223) - max(j - 3, 0) + 1);
    const float nc16 = (float)(min(j + 8, 223) - max(j - 7, 0) + 1);

    __shared__ float4 s_tab[H_];
    for (int i = c; i < H_; i += 64) {
        float nr2  = (float)(min(i + 1, 223) - i + 1);
        float nr4  = (float)(min(i + 2, 223) - max(i - 1, 0) + 1);
        float nr8  = (float)(min(i + 4, 223) - max(i - 3, 0) + 1);
        float nr16 = (float)(min(i + 8, 223) - max(i - 7, 0) + 1);
        s_tab[i] = make_float4(EPS_ - nr2 * nc2 * mi,  EPS_ - nr4 * nc4 * mi,
                               EPS_ - nr8 * nc8 * mi,  EPS_ - nr16 * nc16 * mi);
    }
    __syncthreads();

    // Base pointers at relative row 0 == actual row (i0 - 7), i.e. padded row (i0 + 1).
    // H8 family offsets: +0 (col j), +4*C_ (col j+4), +8*C_ (col j+8).
    // H2 family offsets: +0 (col j), +1*C_ (col j+1), +2*C_ (col j+2).
    const float* bH8 = g_H8 + (size_t)b * RT_ * ST8 + (size_t)(i0 + 1) * ST8 + j * C_ + c;
    const float* bH2 = g_H2 + (size_t)b * RT_ * ST2 + (size_t)(i0 + 1) * ST2 + j * C_ + c;
    const float* xr  = x   + ((size_t)b * H_ * W_ + j) * C_ + c + (size_t)i0 * STX;
    float*       orr = out + ((size_t)b * H_ * W_ + j) * C_ + c + (size_t)i0 * STX;

    float r2[2], r4[4], r8[8], r16[16];

    // prefill rel rows 0..14 (== actual i0-7 .. i0+7); pads are zero
    #pragma unroll
    for (int d = -7; d <= 7; d++) {
        const int rr = d + 7;
        r16[rr & 15] = bH8[rr * ST8] + bH8[rr * ST8 + 8 * C_];
        if (d >= -3 && d <= 3) r8[d + 3] = bH8[rr * ST8 + 4 * C_];
        if (d >= -1 && d <= 1) r4[d + 1] = bH2[rr * ST2] + bH2[rr * ST2 + 2 * C_];
        if (d == 0)            r2[0]     = bH2[rr * ST2 + C_];
    }

    #pragma unroll
    for (int base = 0; base < CH_; base += 16) {
        #pragma unroll
        for (int p = 0; p < 8; p++) {
            const int u = 2 * p;
            if (base + u >= CH_) break;
            const int rel = base + u;            // compile-time

            // ---- insert first new rows (i+8 / i+4 / i+2 / i+1) ----
            r16[(u + 15) & 15] = bH8[(rel + 15) * ST8] + bH8[(rel + 15) * ST8 + 8 * C_];
            r8 [(u + 7) & 7]   = bH8[(rel + 11) * ST8 + 4 * C_];
            r4 [(u + 3) & 3]   = bH2[(rel + 9) * ST2] + bH2[(rel + 9) * ST2 + 2 * C_];
            r2 [(u + 1) & 1]   = bH2[(rel + 8) * ST2 + C_];

            // ---- shared cores (excluded slot folded as +0.f) ----
            #define Z16(s) (((s) == (u & 15)) ? 0.f : r16[s])
            const float A16 =
                ((((Z16(0)+Z16(1))+(Z16(2)+Z16(3)))+((Z16(4)+Z16(5))+(Z16(6)+Z16(7))))
               + (((Z16(8)+Z16(9))+(Z16(10)+Z16(11)))+((Z16(12)+Z16(13))+(Z16(14)+Z16(15)))));
            #undef Z16
            #define Z8(s) (((s) == (u & 7)) ? 0.f : r8[s])
            const float A8 = ((Z8(0)+Z8(1))+(Z8(2)+Z8(3)))+((Z8(4)+Z8(5))+(Z8(6)+Z8(7)));
            #undef Z8
            #define Z4(s) (((s) == (u & 3)) ? 0.f : r4[s])
            const float A4 = (Z4(0)+Z4(1))+(Z4(2)+Z4(3));
            #undef Z4

            const float m16_0 = A16 + r16[u & 15];
            const float m8_0  = A8  + r8[u & 7];
            const float m4_0  = A4  + r4[u & 3];
            const float m2_0  = r2[0] + r2[1];

            // ---- insert second new rows (i+9 / i+5 / i+3 / i+2) into freed slots ----
            r16[u & 15] = bH8[(rel + 16) * ST8] + bH8[(rel + 16) * ST8 + 8 * C_];
            r8 [u & 7]  = bH8[(rel + 12) * ST8 + 4 * C_];
            r4 [u & 3]  = bH2[(rel + 10) * ST2] + bH2[(rel + 10) * ST2 + 2 * C_];
            r2 [u & 1]  = bH2[(rel + 9) * ST2 + C_];

            const float m16_1 = A16 + r16[u & 15];
            const float m8_1  = A8  + r8[u & 7];
            const float m4_1  = A4  + r4[u & 3];
            const float m2_1  = r2[(u + 1) & 1] + r2[u & 1];

            const float sig0 = tail_sig(m2_0, m4_0, m8_0, m16_0, s_tab[i0 + rel],     tc, s_aw, c);
            const float sig1 = tail_sig(m2_1, m4_1, m8_1, m16_1, s_tab[i0 + rel + 1], tc, s_aw, c);
            orr[rel * STX]       = xr[rel * STX]       + sig0;
            orr[(rel + 1) * STX] = xr[(rel + 1) * STX] + sig1;
        }
    }
}

extern "C" void kernel_launch(void* const* d_in, const int* in_sizes, int n_in,
                              void* d_out, int out_size) {
    const float* x    = (const float*)d_in[0];
    const float* olsw = (const float*)d_in[1];
    const float* anch = (const float*)d_in[2];
    const float* wdth = (const float*)d_in[3];
    const float* gmm  = (const float*)d_in[4];
    const float* bta  = (const float*)d_in[5];
    const float* mea  = (const float*)d_in[6];
    const float* vrr  = (const float*)d_in[7];
    float* out = (float*)d_out;

    kA<<<dim3(H_, B_), dim3(C_, 4)>>>(x);
    kB<<<dim3(W_, H_ / CH_, B_), C_>>>(x, olsw, anch, wdth, gmm, bta, mea, vrr, out);
}